// round 2
// baseline (speedup 1.0000x reference)
#include <cuda_runtime.h>

// Problem: MVFModuleChannelsLast — B=8, T=40, H=32, W=32, C=64, C_MVF=32, K=3
// out[...,0:32] = relu(convT + convH + convW on x[...,0:32]); out[...,32:64] = x[...,32:64]
// Center taps of the three separable convs act on the same voxel -> merged:
// 7 matrices of 32x32 instead of 9 (22% FLOP cut).

#define Bv 8
#define Tv 40
#define Hv 32
#define Wv 32
#define Cv 64

__device__ __forceinline__ unsigned long long pack2(float a) {
    unsigned long long r;
    unsigned int ai = __float_as_uint(a);
    asm("mov.b64 %0, {%1, %1};" : "=l"(r) : "r"(ai));
    return r;
}
__device__ __forceinline__ void fma2(unsigned long long &d, unsigned long long a, unsigned long long b) {
    asm("fma.rn.f32x2 %0, %1, %2, %0;" : "+l"(d) : "l"(a), "l"(b));
}
__device__ __forceinline__ void unpack2(unsigned long long v, float &lo, float &hi) {
    unsigned int l, h;
    asm("mov.b64 {%0, %1}, %2;" : "=r"(l), "=r"(h) : "l"(v));
    lo = __uint_as_float(l);
    hi = __uint_as_float(h);
}

__global__ __launch_bounds__(128) void mvf_kernel(
    const float* __restrict__ x, const float* __restrict__ wT,
    const float* __restrict__ wH, const float* __restrict__ wW,
    float* __restrict__ out)
{
    // Weight smem: 7 matrices [m][ci][co], co-pairs stored as u64 for f32x2 FMAs.
    // m0 = merged centers; m1/m2 = wT[0]/wT[2]; m3/m4 = wH[0]/wH[2]; m5/m6 = wW[0]/wW[2]
    __shared__ unsigned long long wsm[7 * 512];
    float* wsf = (float*)wsm;
    const int tid = threadIdx.y * 32 + threadIdx.x;
    for (int i = tid; i < 1024; i += 128) {
        wsf[i]        = wT[1024 + i] + wH[1024 + i] + wW[1024 + i];
        wsf[1024 + i] = wT[i];
        wsf[2048 + i] = wT[2048 + i];
        wsf[3072 + i] = wH[i];
        wsf[4096 + i] = wH[2048 + i];
        wsf[5120 + i] = wW[i];
        wsf[6144 + i] = wW[2048 + i];
    }
    __syncthreads();

    const int w  = threadIdx.x;
    const int bt = blockIdx.x;
    const int b  = bt / Tv;
    const int t  = bt - b * Tv;
    const int h0 = blockIdx.y * 8 + threadIdx.y * 2;   // this thread: voxels (h0, h0+1)

    const long vox0 = ((((long)b * Tv + t) * Hv + h0) * Wv + w) * Cv;
    const float* base0 = x + vox0;

    // neighbor element offsets, m order: center, t-1, t+1, h-1, h+1, w-1, w+1
    const long moff[7] = {0, -65536, 65536, -2048, 2048, -64, 64};
    // validity bitmask per voxel (bit m)
    const unsigned int tb = ((unsigned)(t > 0) << 1) | ((unsigned)(t < Tv - 1) << 2);
    const unsigned int wb = ((unsigned)(w > 0) << 5) | ((unsigned)(w < Wv - 1) << 6);
    const unsigned int vm0 = 1u | tb | ((unsigned)(h0 > 0) << 3) | (1u << 4) | wb;
    const unsigned int vm1 = 1u | tb | (1u << 3) | ((unsigned)(h0 < Hv - 2) << 4) | wb;

    unsigned long long acc0[16], acc1[16];
    #pragma unroll
    for (int j = 0; j < 16; ++j) { acc0[j] = 0ull; acc1[j] = 0ull; }

    #pragma unroll 1
    for (int m = 0; m < 7; ++m) {
        // Predicated addressing: invalid neighbors read the (always-valid) center
        // voxel and the result is zeroed — keeps the LDG unconditional & uniform.
        const bool g0 = (vm0 >> m) & 1u;
        const bool g1 = (vm1 >> m) & 1u;
        const long off = moff[m];
        const float4* p0 = (const float4*)(base0 + (g0 ? off : 0));
        const float4* p1 = (const float4*)(base0 + Wv * Cv + (g1 ? off : 0));
        const float z0 = g0 ? 1.f : 0.f;
        const float z1 = g1 ? 1.f : 0.f;
        const unsigned long long* wm = wsm + m * 512;

        #pragma unroll 2
        for (int c4 = 0; c4 < 8; ++c4) {
            float4 xq0 = __ldg(p0 + c4);
            float4 xq1 = __ldg(p1 + c4);
            const unsigned long long* wr = wm + c4 * 64;
            #pragma unroll
            for (int s = 0; s < 4; ++s) {
                float a0 = (s == 0) ? xq0.x : (s == 1) ? xq0.y : (s == 2) ? xq0.z : xq0.w;
                float a1 = (s == 0) ? xq1.x : (s == 1) ? xq1.y : (s == 2) ? xq1.z : xq1.w;
                unsigned long long xx0 = pack2(a0 * z0);
                unsigned long long xx1 = pack2(a1 * z1);
                #pragma unroll
                for (int j = 0; j < 16; ++j) {
                    unsigned long long wv = wr[s * 16 + j];  // broadcast LDS.64, conflict-free
                    fma2(acc0[j], xx0, wv);
                    fma2(acc1[j], xx1, wv);
                }
            }
        }
    }

    // Epilogue: relu + store conv channels, copy skip channels. All float4.
    float* o0 = out + vox0;
    float* o1 = o0 + Wv * Cv;
    const float* base1 = base0 + Wv * Cv;
    #pragma unroll
    for (int j = 0; j < 8; ++j) {
        float a, bb, c, d;
        unpack2(acc0[2 * j], a, bb);
        unpack2(acc0[2 * j + 1], c, d);
        ((float4*)o0)[j] = make_float4(fmaxf(a, 0.f), fmaxf(bb, 0.f), fmaxf(c, 0.f), fmaxf(d, 0.f));
        unpack2(acc1[2 * j], a, bb);
        unpack2(acc1[2 * j + 1], c, d);
        ((float4*)o1)[j] = make_float4(fmaxf(a, 0.f), fmaxf(bb, 0.f), fmaxf(c, 0.f), fmaxf(d, 0.f));
    }
    #pragma unroll
    for (int q = 8; q < 16; ++q) {
        ((float4*)o0)[q] = __ldg((const float4*)base0 + q);
        ((float4*)o1)[q] = __ldg((const float4*)base1 + q);
    }
}

extern "C" void kernel_launch(void* const* d_in, const int* in_sizes, int n_in,
                              void* d_out, int out_size) {
    const float* x  = (const float*)d_in[0];
    const float* wT = (const float*)d_in[1];
    const float* wH = (const float*)d_in[2];
    const float* wW = (const float*)d_in[3];
    dim3 grid(Bv * Tv, Hv / 8);  // 320 x 4 = 1280 CTAs
    dim3 block(32, 4);           // 128 threads, 2 voxels/thread
    mvf_kernel<<<grid, block>>>(x, wT, wH, wW, (float*)d_out);
}